// round 5
// baseline (speedup 1.0000x reference)
#include <cuda_runtime.h>

#define Bq  256
#define Tq  2000
#define Fq  80
#define Hq  64
#define G3q 192
#define Oq  29

// Precomputed layer-0 input projection: gx0[b][t][g] (393 MB static device scratch)
__device__ float g_gx0[(size_t)Bq * Tq * G3q];

// MUFU.TANH (sm_75+): 1 MUFU, ~1e-5 abs err
__device__ __forceinline__ float tanha(float x) {
    float y;
    asm("tanh.approx.f32 %0, %1;" : "=f"(y) : "f"(x));
    return y;
}
__device__ __forceinline__ float siga(float x) {
    return fmaf(tanha(0.5f * x), 0.5f, 0.5f);
}

// Blackwell packed f32x2 FMA (PTX-only; ptxas never auto-fuses)
__device__ __forceinline__ float2 ffma2(float2 a, float2 b, float2 c) {
    float2 d;
    asm("fma.rn.f32x2 %0, %1, %2, %3;"
        : "=l"(*reinterpret_cast<unsigned long long*>(&d))
        : "l"(*reinterpret_cast<unsigned long long*>(&a)),
          "l"(*reinterpret_cast<unsigned long long*>(&b)),
          "l"(*reinterpret_cast<unsigned long long*>(&c)));
    return d;
}

// ---------------------------------------------------------------------------
// Kernel 1: gx0 = x @ W_ih0^T + b_ih0   (time-parallel GEMM, t-pair f32x2)
// ---------------------------------------------------------------------------
__global__ __launch_bounds__(192) void gx0_kernel(
    const float* __restrict__ x,
    const float* __restrict__ W_ih0,
    const float* __restrict__ b_ih0)
{
    extern __shared__ float sm[];
    float* Wsh = sm;               // [80][192]  W_ih0 transposed
    float* bsh = Wsh + Fq * G3q;   // [192]
    float* xs  = bsh + G3q;        // [80][20]   x tile transposed

    const int tid    = threadIdx.x;
    const int b      = blockIdx.x >> 2;
    const int t0base = (blockIdx.x & 3) * 500;

    for (int idx = tid; idx < G3q * Fq; idx += 192) {
        int gg = idx / Fq, f = idx % Fq;
        Wsh[f * G3q + gg] = W_ih0[idx];
    }
    if (tid < G3q) bsh[tid] = b_ih0[tid];
    __syncthreads();

    const int g = tid;
    for (int c = 0; c < 25; ++c) {
        int t0 = t0base + c * 20;
        for (int idx = tid; idx < 20 * Fq; idx += 192) {
            int tt = idx / Fq, f = idx % Fq;
            xs[f * 20 + tt] = x[((size_t)b * Tq + t0 + tt) * Fq + f];
        }
        __syncthreads();

        float2 acc[10];
        float bias = bsh[g];
        #pragma unroll
        for (int i = 0; i < 10; ++i) acc[i] = make_float2(bias, bias);

        #pragma unroll 4
        for (int f = 0; f < Fq; ++f) {
            float w = Wsh[f * G3q + g];
            float2 w2 = make_float2(w, w);
            const float4* xv = reinterpret_cast<const float4*>(&xs[f * 20]);
            #pragma unroll
            for (int q = 0; q < 5; ++q) {
                float4 v = xv[q];
                acc[q * 2 + 0] = ffma2(w2, make_float2(v.x, v.y), acc[q * 2 + 0]);
                acc[q * 2 + 1] = ffma2(w2, make_float2(v.z, v.w), acc[q * 2 + 1]);
            }
        }
        #pragma unroll
        for (int i = 0; i < 10; ++i) {
            g_gx0[((size_t)b * Tq + t0 + 2 * i + 0) * G3q + g] = acc[i].x;
            g_gx0[((size_t)b * Tq + t0 + 2 * i + 1) * G3q + g] = acc[i].y;
        }
        __syncthreads();
    }
}

// ---------------------------------------------------------------------------
// Kernel 2: fused 2-layer GRU + FC. Register weights; 3 barriers/step;
// MUFU.TANH activations spread across 128 threads per group.
//   grp A (tid 0..191):   W_hh0 rows, layer 0 @ time i
//   grp B (tid 192..383): W_ih1 rows, layer 1 @ time i-1
//   grp C (tid 384..575): W_hh1 rows, layer 1 @ time i-1 (+ h1 act/update)
// ---------------------------------------------------------------------------
__global__ __launch_bounds__(576, 1) void rnn_kernel(
    const float* __restrict__ h_in,
    const float* __restrict__ W_hh0, const float* __restrict__ b_hh0,
    const float* __restrict__ W_ih1, const float* __restrict__ W_hh1,
    const float* __restrict__ b_ih1, const float* __restrict__ b_hh1,
    const float* __restrict__ W_fc,  const float* __restrict__ b_fc,
    float* __restrict__ out, int write_hidden)
{
    __shared__ float h0s[2][2][Hq];     // [parity][batch][64]
    __shared__ float h1s[2][Hq];        // [batch][64]
    __shared__ float smA[2][128];       // layer0 r,z pre-acts (gx+d)
    __shared__ float smAngx[2][Hq];     // layer0 n-row gx
    __shared__ float smAnd[2][Hq];      // layer0 n-row h-dot
    __shared__ float smB[2][G3q];       // layer1 x-side dots (all rows)
    __shared__ float smC[2][G3q];       // layer1 h-side dots (all rows)

    const int tid = threadIdx.x;
    const int grp = tid / G3q;          // 0=A, 1=B, 2=C
    const int g   = tid - grp * G3q;    // row 0..191
    const int b0  = blockIdx.x * 2;
    const int b1  = b0 + 1;

    // --- weight row -> registers ---
    const float* Wsrc = (grp == 0) ? W_hh0 : (grp == 1) ? W_ih1 : W_hh1;
    float4 w[16];
    #pragma unroll
    for (int i = 0; i < 16; ++i)
        w[i] = reinterpret_cast<const float4*>(Wsrc)[g * 16 + i];
    const float bias = (grp == 0) ? b_hh0[g] : (grp == 1) ? b_ih1[g] : b_hh1[g];

    // --- init hidden state (parity 0) ---
    if (tid < Hq)            h0s[0][0][tid]       = h_in[b0 * Hq + tid];
    else if (tid < 2 * Hq)   h0s[0][1][tid - 64]  = h_in[b1 * Hq + tid - 64];
    else if (tid < 3 * Hq)   h1s[0][tid - 128]    = h_in[Bq * Hq + b0 * Hq + tid - 128];
    else if (tid < 4 * Hq)   h1s[1][tid - 192]    = h_in[Bq * Hq + b1 * Hq + tid - 192];
    __syncthreads();

    const float* gxp0 = g_gx0 + (size_t)b0 * Tq * G3q + g;
    const float* gxp1 = g_gx0 + (size_t)b1 * Tq * G3q + g;
    float gxA0 = 0.0f, gxA1 = 0.0f;
    if (grp == 0) { gxA0 = gxp0[0]; gxA1 = gxp1[0]; }

    for (int i = 0; i <= Tq; ++i) {
        const int p = i & 1;

        // prefetch next step's gx (group A; a full step of slack)
        float nx0 = 0.0f, nx1 = 0.0f;
        if (grp == 0 && i + 1 < Tq) {
            nx0 = __ldg(gxp0 + (size_t)(i + 1) * G3q);
            nx1 = __ldg(gxp1 + (size_t)(i + 1) * G3q);
        }

        // --- register-weight dot products (both batches) ---
        const float* hv0 = (grp == 2) ? h1s[0] : h0s[p][0];
        const float* hv1 = (grp == 2) ? h1s[1] : h0s[p][1];
        float2 aA0 = make_float2(bias, 0.0f), aB0 = make_float2(0.0f, 0.0f);
        float2 aA1 = make_float2(bias, 0.0f), aB1 = make_float2(0.0f, 0.0f);
        #pragma unroll
        for (int k = 0; k < 16; ++k) {
            float4 wv = w[k];
            float4 u  = reinterpret_cast<const float4*>(hv0)[k];
            float4 v  = reinterpret_cast<const float4*>(hv1)[k];
            aA0 = ffma2(make_float2(wv.x, wv.y), make_float2(u.x, u.y), aA0);
            aB0 = ffma2(make_float2(wv.z, wv.w), make_float2(u.z, u.w), aB0);
            aA1 = ffma2(make_float2(wv.x, wv.y), make_float2(v.x, v.y), aA1);
            aB1 = ffma2(make_float2(wv.z, wv.w), make_float2(v.z, v.w), aB1);
        }
        float d0 = (aA0.x + aA0.y) + (aB0.x + aB0.y);
        float d1 = (aA1.x + aA1.y) + (aB1.x + aB1.y);

        if (grp == 0) {
            // ---- layer 0, time i ----
            if (g < 128) {                     // r,z rows: publish pre-acts
                smA[0][g] = gxA0 + d0;
                smA[1][g] = gxA1 + d1;
            } else {                           // n rows: publish gx and dot
                int j = g - 128;
                smAngx[0][j] = gxA0;  smAnd[0][j] = d0;
                smAngx[1][j] = gxA1;  smAnd[1][j] = d1;
            }
            asm volatile("bar.sync 1, 192;" ::: "memory");
            if (i < Tq && g < 128) {           // 128 act threads, 1 batch each
                int b = g >> 6, j = g & 63;
                float r = siga(smA[b][j]);
                float z = siga(smA[b][64 + j]);
                float n = tanha(fmaf(r, smAnd[b][j], smAngx[b][j]));
                h0s[p ^ 1][b][j] = (1.0f - z) * n + z * h0s[p][b][j];
            }
            gxA0 = nx0; gxA1 = nx1;
        } else if (grp == 1) {
            // ---- layer 1 x-side dots ----
            smB[0][g] = d0; smB[1][g] = d1;
            asm volatile("bar.sync 2, 384;" ::: "memory");
        } else {
            // ---- layer 1 h-side dots + act/update ----
            smC[0][g] = d0; smC[1][g] = d1;
            asm volatile("bar.sync 2, 384;" ::: "memory");
            if (i > 0 && g < 128) {            // 128 act threads, 1 batch each
                int b = g >> 6, j = g & 63;
                float r = siga(smB[b][j] + smC[b][j]);
                float z = siga(smB[b][64 + j] + smC[b][64 + j]);
                float n = tanha(fmaf(r, smC[b][128 + j], smB[b][128 + j]));
                h1s[b][j] = (1.0f - z) * n + z * h1s[b][j];
            }
        }
        __syncthreads();   // h0 handoff A->B, h1 C-act->C-dots, SMEM WAR
    }

    // ---- epilogue ----
    const int pf = Tq & 1;  // parity holding h0^(T)
    if (write_hidden && tid < 2 * Hq) {
        int b = tid >> 6, j = tid & 63;
        out[Bq * Oq + (b0 + b) * Hq + j]           = h0s[pf][b][j];
        out[Bq * Oq + Bq * Hq + (b0 + b) * Hq + j] = h1s[b][j];
    }
    if (tid < 2 * Oq) {
        int b = tid / Oq, o = tid - b * Oq;
        float acc = b_fc[o];
        #pragma unroll
        for (int j = 0; j < Hq; ++j)
            acc = fmaf(fmaxf(h1s[b][j], 0.0f), __ldg(&W_fc[o * Hq + j]), acc);
        out[(b0 + b) * Oq + o] = acc;
    }
}

// ---------------------------------------------------------------------------
extern "C" void kernel_launch(void* const* d_in, const int* in_sizes, int n_in,
                              void* d_out, int out_size) {
    const float* x     = (const float*)d_in[0];
    const float* h     = (const float*)d_in[1];
    const float* W_ih0 = (const float*)d_in[2];
    const float* W_hh0 = (const float*)d_in[3];
    const float* b_ih0 = (const float*)d_in[4];
    const float* b_hh0 = (const float*)d_in[5];
    const float* W_ih1 = (const float*)d_in[6];
    const float* W_hh1 = (const float*)d_in[7];
    const float* b_ih1 = (const float*)d_in[8];
    const float* b_hh1 = (const float*)d_in[9];
    const float* W_fc  = (const float*)d_in[10];
    const float* b_fc  = (const float*)d_in[11];
    float* out = (float*)d_out;

    const int smem1 = (Fq * G3q + G3q + Fq * 20) * (int)sizeof(float);  // 68,608 B

    cudaFuncSetAttribute(gx0_kernel, cudaFuncAttributeMaxDynamicSharedMemorySize, smem1);

    gx0_kernel<<<Bq * 4, 192, smem1>>>(x, W_ih0, b_ih0);

    int write_hidden = (out_size >= Bq * Oq + 2 * Bq * Hq) ? 1 : 0;
    rnn_kernel<<<Bq / 2, 576>>>(h, W_hh0, b_hh0,
                                W_ih1, W_hh1, b_ih1, b_hh1,
                                W_fc, b_fc, out, write_hidden);
}

// round 6
// speedup vs baseline: 1.6273x; 1.6273x over previous
#include <cuda_runtime.h>

#define Bq  256
#define Tq  2000
#define Fq  80
#define Hq  64
#define G3q 192
#define Oq  29

// Precomputed layer-0 input projection: gx0[b][t][g] (393 MB static device scratch)
__device__ float g_gx0[(size_t)Bq * Tq * G3q];

// MUFU.TANH (sm_75+)
__device__ __forceinline__ float tanha(float x) {
    float y;
    asm("tanh.approx.f32 %0, %1;" : "=f"(y) : "f"(x));
    return y;
}
__device__ __forceinline__ float siga(float x) {
    return fmaf(tanha(0.5f * x), 0.5f, 0.5f);
}

// Blackwell packed f32x2 FMA (PTX-only; ptxas never auto-fuses)
__device__ __forceinline__ float2 ffma2(float2 a, float2 b, float2 c) {
    float2 d;
    asm("fma.rn.f32x2 %0, %1, %2, %3;"
        : "=l"(*reinterpret_cast<unsigned long long*>(&d))
        : "l"(*reinterpret_cast<unsigned long long*>(&a)),
          "l"(*reinterpret_cast<unsigned long long*>(&b)),
          "l"(*reinterpret_cast<unsigned long long*>(&c)));
    return d;
}

// ---------------------------------------------------------------------------
// Kernel 1: gx0 = x @ W_ih0^T + b_ih0   (time-parallel GEMM, t-pair f32x2)
// ---------------------------------------------------------------------------
__global__ __launch_bounds__(192) void gx0_kernel(
    const float* __restrict__ x,
    const float* __restrict__ W_ih0,
    const float* __restrict__ b_ih0)
{
    extern __shared__ float sm[];
    float* Wsh = sm;               // [80][192]
    float* bsh = Wsh + Fq * G3q;   // [192]
    float* xs  = bsh + G3q;        // [80][20]

    const int tid    = threadIdx.x;
    const int b      = blockIdx.x >> 2;
    const int t0base = (blockIdx.x & 3) * 500;

    for (int idx = tid; idx < G3q * Fq; idx += 192) {
        int gg = idx / Fq, f = idx % Fq;
        Wsh[f * G3q + gg] = W_ih0[idx];
    }
    if (tid < G3q) bsh[tid] = b_ih0[tid];
    __syncthreads();

    const int g = tid;
    for (int c = 0; c < 25; ++c) {
        int t0 = t0base + c * 20;
        for (int idx = tid; idx < 20 * Fq; idx += 192) {
            int tt = idx / Fq, f = idx % Fq;
            xs[f * 20 + tt] = x[((size_t)b * Tq + t0 + tt) * Fq + f];
        }
        __syncthreads();

        float2 acc[10];
        float bias = bsh[g];
        #pragma unroll
        for (int i = 0; i < 10; ++i) acc[i] = make_float2(bias, bias);

        #pragma unroll 4
        for (int f = 0; f < Fq; ++f) {
            float w = Wsh[f * G3q + g];
            float2 w2 = make_float2(w, w);
            const float4* xv = reinterpret_cast<const float4*>(&xs[f * 20]);
            #pragma unroll
            for (int q = 0; q < 5; ++q) {
                float4 v = xv[q];
                acc[q * 2 + 0] = ffma2(w2, make_float2(v.x, v.y), acc[q * 2 + 0]);
                acc[q * 2 + 1] = ffma2(w2, make_float2(v.z, v.w), acc[q * 2 + 1]);
            }
        }
        #pragma unroll
        for (int i = 0; i < 10; ++i) {
            g_gx0[((size_t)b * Tq + t0 + 2 * i + 0) * G3q + g] = acc[i].x;
            g_gx0[((size_t)b * Tq + t0 + 2 * i + 1) * G3q + g] = acc[i].y;
        }
        __syncthreads();
    }
}

// ---------------------------------------------------------------------------
// Kernel 2: fused 2-layer GRU + FC. Gate-owner threads: each thread owns rows
// {j, 64+j, 128+j}, K-split across lanes (L0: 2-way, L1: 4-way over the concat
// [W_ih1|W_hh1].[h0;h1]); shfl_xor reduction; act + h-update local; ONE
// __syncthreads per step. h kept in padded SMEM quarters (stride 40 floats,
// conflict-free multi-address broadcast).
//   tid   0..127: L0, j = tid>>1, seg = tid&1  (K half; act batch = seg)
//   tid 128..383: L1, j = (tid-128)>>2, seg = (tid-128)&3 (concat quarter;
//                 q0/q1 act for batch 0/1)
// ---------------------------------------------------------------------------
__global__ __launch_bounds__(384, 1) void rnn_kernel(
    const float* __restrict__ h_in,
    const float* __restrict__ W_hh0, const float* __restrict__ b_hh0,
    const float* __restrict__ W_ih1, const float* __restrict__ W_hh1,
    const float* __restrict__ b_ih1, const float* __restrict__ b_hh1,
    const float* __restrict__ W_fc,  const float* __restrict__ b_fc,
    float* __restrict__ out, int write_hidden)
{
    // [parity][batch][quarter of concat [h0;h1]][32 + 8 pad]
    __shared__ float hbuf[2][2][4][40];

    const int tid  = threadIdx.x;
    const int b0   = blockIdx.x * 2;
    const bool isL0 = tid < 128;
    int j, seg;
    if (isL0) { j = tid >> 1; seg = tid & 1; }
    else      { int t = tid - 128; j = t >> 2; seg = t & 3; }

    // --- weight rows (r,z,n) for this thread's K window -> registers ---
    float4 wR[8], wZ[8], wN[8];
    {
        const float4* W;
        int k0;
        if (isL0)          { W = (const float4*)W_hh0; k0 = seg * 8; }
        else if (seg < 2)  { W = (const float4*)W_ih1; k0 = seg * 8; }
        else               { W = (const float4*)W_hh1; k0 = (seg - 2) * 8; }
        #pragma unroll
        for (int k = 0; k < 8; ++k) {
            wR[k] = W[(j      ) * 16 + k0 + k];
            wZ[k] = W[(64 + j ) * 16 + k0 + k];
            wN[k] = W[(128 + j) * 16 + k0 + k];
        }
    }
    // --- biases (act role) ---
    float bR, bZ, bNi = 0.0f, bNh;
    if (isL0) {
        bR = b_hh0[j]; bZ = b_hh0[64 + j]; bNh = b_hh0[128 + j];
    } else {
        bR  = b_ih1[j] + b_hh1[j];
        bZ  = b_ih1[64 + j] + b_hh1[64 + j];
        bNi = b_ih1[128 + j]; bNh = b_hh1[128 + j];
    }

    // --- init state: h0^0 -> buf0 q0/q1 ; h1^0 -> buf1 q2/q3 ; rest zero ---
    if (tid < 256) {
        int b = tid >> 7, idx = tid & 127;
        if (idx < 64) {
            hbuf[0][b][idx >> 5][idx & 31] = h_in[(b0 + b) * Hq + idx];
            hbuf[1][b][idx >> 5][idx & 31] = 0.0f;
        } else {
            int jj = idx - 64;
            hbuf[1][b][2 + (jj >> 5)][jj & 31] = h_in[Bq * Hq + (b0 + b) * Hq + jj];
            hbuf[0][b][2 + (jj >> 5)][jj & 31] = 0.0f;
        }
    }
    __syncthreads();

    // gx stream (L0 act role: batch = seg)
    const float* gxp = g_gx0 + (size_t)(b0 + (isL0 ? seg : 0)) * Tq * G3q;
    float gxR = 0.0f, gxZ = 0.0f, gxN = 0.0f;
    if (isL0) { gxR = gxp[j]; gxZ = gxp[64 + j]; gxN = gxp[128 + j]; }

    // previous h element owned by this act thread
    float hprev = 0.0f;
    if (isL0)          hprev = h_in[(b0 + seg) * Hq + j];
    else if (seg < 2)  hprev = h_in[Bq * Hq + (b0 + seg) * Hq + j];

    for (int i = 0; i <= Tq; ++i) {
        const int p = i & 1;

        // prefetch next step's gx (hidden behind the whole step)
        float nR = 0.0f, nZ = 0.0f, nN = 0.0f;
        if (isL0 && i + 1 < Tq) {
            const float* gq = gxp + (size_t)(i + 1) * G3q;
            nR = __ldg(gq + j); nZ = __ldg(gq + 64 + j); nN = __ldg(gq + 128 + j);
        }

        // --- partial dots over this thread's K window, both batches ---
        const float4* u4 = (const float4*)hbuf[p][0][seg];
        const float4* v4 = (const float4*)hbuf[p][1][seg];
        float2 aR0 = {0,0}, aZ0 = {0,0}, aN0 = {0,0};
        float2 aR1 = {0,0}, aZ1 = {0,0}, aN1 = {0,0};
        #pragma unroll
        for (int k = 0; k < 8; ++k) {
            float4 u = u4[k], v = v4[k];
            float2 ulo = make_float2(u.x, u.y), uhi = make_float2(u.z, u.w);
            float2 vlo = make_float2(v.x, v.y), vhi = make_float2(v.z, v.w);
            float2 rlo = make_float2(wR[k].x, wR[k].y), rhi = make_float2(wR[k].z, wR[k].w);
            float2 zlo = make_float2(wZ[k].x, wZ[k].y), zhi = make_float2(wZ[k].z, wZ[k].w);
            float2 nlo = make_float2(wN[k].x, wN[k].y), nhi = make_float2(wN[k].z, wN[k].w);
            aR0 = ffma2(rlo, ulo, aR0);  aR0 = ffma2(rhi, uhi, aR0);
            aZ0 = ffma2(zlo, ulo, aZ0);  aZ0 = ffma2(zhi, uhi, aZ0);
            aN0 = ffma2(nlo, ulo, aN0);  aN0 = ffma2(nhi, uhi, aN0);
            aR1 = ffma2(rlo, vlo, aR1);  aR1 = ffma2(rhi, vhi, aR1);
            aZ1 = ffma2(zlo, vlo, aZ1);  aZ1 = ffma2(zhi, vhi, aZ1);
            aN1 = ffma2(nlo, vlo, aN1);  aN1 = ffma2(nhi, vhi, aN1);
        }
        float dR0 = aR0.x + aR0.y, dZ0 = aZ0.x + aZ0.y, dN0 = aN0.x + aN0.y;
        float dR1 = aR1.x + aR1.y, dZ1 = aZ1.x + aZ1.y, dN1 = aN1.x + aN1.y;

        if (isL0) {
            // 2-way butterfly; then local act + h0 update (owner keeps hprev)
            dR0 += __shfl_xor_sync(0xffffffffu, dR0, 1);
            dZ0 += __shfl_xor_sync(0xffffffffu, dZ0, 1);
            dN0 += __shfl_xor_sync(0xffffffffu, dN0, 1);
            dR1 += __shfl_xor_sync(0xffffffffu, dR1, 1);
            dZ1 += __shfl_xor_sync(0xffffffffu, dZ1, 1);
            dN1 += __shfl_xor_sync(0xffffffffu, dN1, 1);
            if (i < Tq) {
                float dR = seg ? dR1 : dR0;
                float dZ = seg ? dZ1 : dZ0;
                float dN = seg ? dN1 : dN0;
                float r = siga(gxR + dR + bR);
                float z = siga(gxZ + dZ + bZ);
                float n = tanha(fmaf(r, dN + bNh, gxN));   // gxN includes b_ih0
                float hn = (1.0f - z) * n + z * hprev;
                hprev = hn;
                hbuf[p ^ 1][seg][j >> 5][j & 31] = hn;
            }
            gxR = nR; gxZ = nZ; gxN = nN;
        } else {
            // keep x-side and h-side n-dots separate through the reduction
            float dNx0 = (seg < 2) ? dN0 : 0.0f;
            float dNh0 = (seg < 2) ? 0.0f : dN0;
            float dNx1 = (seg < 2) ? dN1 : 0.0f;
            float dNh1 = (seg < 2) ? 0.0f : dN1;
            #pragma unroll
            for (int m = 1; m <= 2; m <<= 1) {
                dR0  += __shfl_xor_sync(0xffffffffu, dR0,  m);
                dZ0  += __shfl_xor_sync(0xffffffffu, dZ0,  m);
                dNx0 += __shfl_xor_sync(0xffffffffu, dNx0, m);
                dNh0 += __shfl_xor_sync(0xffffffffu, dNh0, m);
                dR1  += __shfl_xor_sync(0xffffffffu, dR1,  m);
                dZ1  += __shfl_xor_sync(0xffffffffu, dZ1,  m);
                dNx1 += __shfl_xor_sync(0xffffffffu, dNx1, m);
                dNh1 += __shfl_xor_sync(0xffffffffu, dNh1, m);
            }
            if (i > 0 && seg < 2) {
                float dR  = seg ? dR1  : dR0;
                float dZ  = seg ? dZ1  : dZ0;
                float dNx = seg ? dNx1 : dNx0;
                float dNh = seg ? dNh1 : dNh0;
                float r = siga(dR + bR);
                float z = siga(dZ + bZ);
                float n = tanha(fmaf(r, dNh + bNh, dNx + bNi));
                float hn = (1.0f - z) * n + z * hprev;
                hprev = hn;
                hbuf[p ^ 1][seg][2 + (j >> 5)][j & 31] = hn;
            }
        }
        __syncthreads();   // publish h0^{i+1}, h1^{i} for next iteration
    }

    // ---- epilogue: h0 final in buf0 q0/q1, h1 final in buf1 q2/q3 ----
    if (write_hidden && tid < 2 * Hq) {
        int b = tid >> 6, jj = tid & 63;
        out[Bq * Oq + (b0 + b) * Hq + jj]           = hbuf[0][b][jj >> 5][jj & 31];
        out[Bq * Oq + Bq * Hq + (b0 + b) * Hq + jj] = hbuf[1][b][2 + (jj >> 5)][jj & 31];
    }
    if (tid < 2 * Oq) {
        int b = tid / Oq, o = tid - b * Oq;
        float acc = b_fc[o];
        #pragma unroll
        for (int jj = 0; jj < Hq; ++jj)
            acc = fmaf(fmaxf(hbuf[1][b][2 + (jj >> 5)][jj & 31], 0.0f),
                       __ldg(&W_fc[o * Hq + jj]), acc);
        out[(b0 + b) * Oq + o] = acc;
    }
}

// ---------------------------------------------------------------------------
extern "C" void kernel_launch(void* const* d_in, const int* in_sizes, int n_in,
                              void* d_out, int out_size) {
    const float* x     = (const float*)d_in[0];
    const float* h     = (const float*)d_in[1];
    const float* W_ih0 = (const float*)d_in[2];
    const float* W_hh0 = (const float*)d_in[3];
    const float* b_ih0 = (const float*)d_in[4];
    const float* b_hh0 = (const float*)d_in[5];
    const float* W_ih1 = (const float*)d_in[6];
    const float* W_hh1 = (const float*)d_in[7];
    const float* b_ih1 = (const float*)d_in[8];
    const float* b_hh1 = (const float*)d_in[9];
    const float* W_fc  = (const float*)d_in[10];
    const float* b_fc  = (const float*)d_in[11];
    float* out = (float*)d_out;

    const int smem1 = (Fq * G3q + G3q + Fq * 20) * (int)sizeof(float);  // 68,608 B
    cudaFuncSetAttribute(gx0_kernel, cudaFuncAttributeMaxDynamicSharedMemorySize, smem1);

    gx0_kernel<<<Bq * 4, 192, smem1>>>(x, W_ih0, b_ih0);

    int write_hidden = (out_size >= Bq * Oq + 2 * Bq * Hq) ? 1 : 0;
    rnn_kernel<<<Bq / 2, 384>>>(h, W_hh0, b_hh0,
                                W_ih1, W_hh1, b_ih1, b_hh1,
                                W_fc, b_fc, out, write_hidden);
}